// round 9
// baseline (speedup 1.0000x reference)
#include <cuda_runtime.h>
#include <cuda_bf16.h>
#include <cstdint>
#include <math.h>

// Normalized embeddings scratch (bf16): 8192 * 256 * 2B = 4 MB, L2-resident.
__device__ __nv_bfloat16 g_en[8192 * 256];

// ---------------------------------------------------------------------------
// Kernel 1: row-normalize embeddings (fp32 -> bf16). One warp per row, D=256.
// Also zeroes the (poisoned) output scalar from block 0.
// ---------------------------------------------------------------------------
__global__ void normalize_kernel(const float* __restrict__ emb, int B,
                                 float* __restrict__ out) {
    if (blockIdx.x == 0 && threadIdx.x == 0) out[0] = 0.0f;

    const int warpId = threadIdx.x >> 5;
    const int lane   = threadIdx.x & 31;
    const int row    = blockIdx.x * 8 + warpId;
    if (row >= B) return;

    const float4* p = reinterpret_cast<const float4*>(emb + (size_t)row * 256);
    float4 v0 = p[lane];
    float4 v1 = p[lane + 32];

    float ss = v0.x * v0.x + v0.y * v0.y + v0.z * v0.z + v0.w * v0.w
             + v1.x * v1.x + v1.y * v1.y + v1.z * v1.z + v1.w * v1.w;
    #pragma unroll
    for (int o = 16; o > 0; o >>= 1) ss += __shfl_xor_sync(0xffffffffu, ss, o);

    const float scale = 1.0f / fmaxf(sqrtf(ss), 1e-8f);

    __nv_bfloat162 a0 = __floats2bfloat162_rn(v0.x * scale, v0.y * scale);
    __nv_bfloat162 a1 = __floats2bfloat162_rn(v0.z * scale, v0.w * scale);
    __nv_bfloat162 b0 = __floats2bfloat162_rn(v1.x * scale, v1.y * scale);
    __nv_bfloat162 b1 = __floats2bfloat162_rn(v1.z * scale, v1.w * scale);

    uint2 ua, ub;
    ua.x = *reinterpret_cast<unsigned*>(&a0);
    ua.y = *reinterpret_cast<unsigned*>(&a1);
    ub.x = *reinterpret_cast<unsigned*>(&b0);
    ub.y = *reinterpret_cast<unsigned*>(&b1);

    uint2* orow = reinterpret_cast<uint2*>(g_en + (size_t)row * 256);
    orow[lane]      = ua;
    orow[lane + 32] = ub;
}

// ---------------------------------------------------------------------------
// Kernel 2: fused cos-GEMM tile + |text - cos| masked reduction.
// mma.sync.m16n8k16 (bf16 -> fp32), in-register mainloop with fragment
// double-buffering (software pipeline: LDSM kc+1 overlaps HMMA kc).
//
// One CTA = one 128x128 upper-triangular tile, K = 256 as four K=64 chunks,
// double-buffered cp.async. text_sim tile fully prefetched via cp.async:
//   group2 = text rows 0-63  -> dedicated TEXT0 region
//   group5 = text rows 64-127 -> buf0 (reused after its last operand read)
// Wait ladder: ch0/ch1 wait 2 | ch2/ch3 wait 1 | epilogue wait 0.
// smem = 2*36864 + 33792 = 105 KB -> 2 CTAs/SM.
// ---------------------------------------------------------------------------
#define LDM_OP     72                      // bf16 elems per padded chunk row
#define ROW_BYTES  144
#define STRIP_B    (128 * ROW_BYTES)       // 18432
#define BUF_B      (2 * STRIP_B)           // 36864 (A strip + B strip)
#define LDM_T      132                     // fp32 elems per padded text row
#define TROW_B     528
#define TEXT0_OFF  (2 * BUF_B)             // 73728
#define TEXT_HALF_B (64 * TROW_B)          // 33792
#define SMEM_TOTAL (TEXT0_OFF + TEXT_HALF_B)   // 107520

#define LDSM4(R0, R1, R2, R3, ADDR)                                          \
    asm volatile("ldmatrix.sync.aligned.m8n8.x4.shared.b16 {%0,%1,%2,%3}, [%4];" \
                 : "=r"(R0), "=r"(R1), "=r"(R2), "=r"(R3) : "r"(ADDR))

#define MMA16816(C, A, B0, B1)                                               \
    asm volatile("mma.sync.aligned.m16n8k16.row.col.f32.bf16.bf16.f32 "      \
                 "{%0,%1,%2,%3}, {%4,%5,%6,%7}, {%8,%9}, {%0,%1,%2,%3};"     \
                 : "+f"((C)[0]), "+f"((C)[1]), "+f"((C)[2]), "+f"((C)[3])    \
                 : "r"((A)[0]), "r"((A)[1]), "r"((A)[2]), "r"((A)[3]),       \
                   "r"(B0), "r"(B1))

// Stage one K=64 operand chunk (A + B strips) into buffer `buf`, commit.
__device__ __forceinline__ void stage_chunk(uint32_t sbase, int buf, int ch,
                                            const char* Ag, const char* Bg,
                                            int tid) {
    const uint32_t aDst = sbase + (uint32_t)buf * BUF_B;
    const uint32_t bDst = aDst + STRIP_B;
    const size_t gchunk = (size_t)ch * 128;
    #pragma unroll
    for (int i = tid; i < 1024; i += 256) {           // 128 rows x 8 x 16B
        const int r = i >> 3;
        const int c = i & 7;
        const uint32_t soff = (uint32_t)r * ROW_BYTES + (uint32_t)c * 16;
        const size_t   goff = (size_t)r * 512 + gchunk + (size_t)c * 16;
        asm volatile("cp.async.cg.shared.global [%0], [%1], 16;"
                     :: "r"(aDst + soff), "l"(Ag + goff) : "memory");
        asm volatile("cp.async.cg.shared.global [%0], [%1], 16;"
                     :: "r"(bDst + soff), "l"(Bg + goff) : "memory");
    }
    asm volatile("cp.async.commit_group;" ::: "memory");
}

// Stage 64 text rows (128 floats each) into smem at `dst` (528 B rows), commit.
__device__ __forceinline__ void stage_text_half(uint32_t dst, const char* tg,
                                                int B, int tid) {
    #pragma unroll
    for (int i = tid; i < 2048; i += 256) {           // 64 rows x 32 x 16B
        const int r = i >> 5;
        const int c = i & 31;
        asm volatile("cp.async.cg.shared.global [%0], [%1], 16;"
                     :: "r"(dst + (uint32_t)r * TROW_B + (uint32_t)c * 16),
                        "l"(tg + (size_t)r * B * 4 + (size_t)c * 16)
                     : "memory");
    }
    asm volatile("cp.async.commit_group;" ::: "memory");
}

// Load all fragments for one kc step.
__device__ __forceinline__ void load_frags(uint32_t bufBase, uint32_t aOff,
                                           uint32_t bOff, int kc,
                                           uint32_t a[2][4], uint32_t b[4][4]) {
    const uint32_t koff = (uint32_t)(kc * 32);       // 16 bf16 = 32 B
    #pragma unroll
    for (int mt = 0; mt < 2; mt++)
        LDSM4(a[mt][0], a[mt][1], a[mt][2], a[mt][3],
              bufBase + aOff + (uint32_t)(mt * 16 * ROW_BYTES) + koff);
    #pragma unroll
    for (int p = 0; p < 4; p++)
        LDSM4(b[p][0], b[p][1], b[p][2], b[p][3],
              bufBase + bOff + (uint32_t)(p * 16 * ROW_BYTES) + koff);
}

__global__ __launch_bounds__(256, 2)
void loss_kernel(const float* __restrict__ text, float* __restrict__ out,
                 int B, float scale) {
    extern __shared__ char smem[];
    uint32_t sbase;
    asm("{ .reg .u64 t; cvta.to.shared.u64 t, %1; cvt.u32.u64 %0, t; }"
        : "=r"(sbase) : "l"((const void*)smem));

    const int tid = threadIdx.x;

    // ---- linear block id -> upper-triangular (by, bx), by <= bx ----
    const int NT = B >> 7;
    int t = blockIdx.x;
    int by = 0;
    while (t >= NT - by) { t -= NT - by; ++by; }
    const int bx = by + t;

    const char* __restrict__ Ag =
        reinterpret_cast<const char*>(g_en + (size_t)by * 128 * 256);
    const char* __restrict__ Bg =
        reinterpret_cast<const char*>(g_en + (size_t)bx * 128 * 256);
    const char* __restrict__ tg = reinterpret_cast<const char*>(
        text + (size_t)(by * 128) * B + (size_t)bx * 128);

    // ---- prologue: g0 = ch0, g1 = ch1, g2 = text rows 0-63 ----
    stage_chunk(sbase, 0, 0, Ag, Bg, tid);
    stage_chunk(sbase, 1, 1, Ag, Bg, tid);
    stage_text_half(sbase + TEXT0_OFF, tg, B, tid);

    // ---- warp / fragment geometry ----
    const int warpId = tid >> 5;
    const int lane   = tid & 31;
    const int wr = warpId & 3;    // 32-row strip
    const int wc = warpId >> 2;   // 64-col strip
    const int grp = lane >> 3;

    const uint32_t aOff =
        (uint32_t)(((wr * 32 + (lane & 15)) * LDM_OP + (lane >> 4) * 8) * 2);
    const uint32_t bOff = (uint32_t)STRIP_B +
        (uint32_t)(((wc * 64 + (grp >> 1) * 8 + (lane & 7)) * LDM_OP + (grp & 1) * 8) * 2);

    float c[2][8][4];
    #pragma unroll
    for (int mt = 0; mt < 2; mt++)
        #pragma unroll
        for (int nt = 0; nt < 8; nt++)
            #pragma unroll
            for (int e = 0; e < 4; e++) c[mt][nt][e] = 0.0f;

    // ---- mainloop over 4 K-chunks, fragment-pipelined inner loop ----
    #pragma unroll
    for (int ch = 0; ch < 4; ch++) {
        if (ch < 2) {
            asm volatile("cp.async.wait_group 2;" ::: "memory");
        } else {
            asm volatile("cp.async.wait_group 1;" ::: "memory");
        }
        __syncthreads();

        const uint32_t bufBase = sbase + (uint32_t)(ch & 1) * BUF_B;

        uint32_t a_cur[2][4], b_cur[4][4];
        load_frags(bufBase, aOff, bOff, 0, a_cur, b_cur);

        #pragma unroll
        for (int kc = 0; kc < 4; kc++) {
            uint32_t a_nxt[2][4], b_nxt[4][4];
            if (kc < 3)    // prefetch next fragments; overlaps MMAs below
                load_frags(bufBase, aOff, bOff, kc + 1, a_nxt, b_nxt);

            #pragma unroll
            for (int mt = 0; mt < 2; mt++)
                #pragma unroll
                for (int nt = 0; nt < 8; nt++)
                    MMA16816(c[mt][nt], a_cur[mt],
                             b_cur[nt >> 1][(nt & 1) * 2],
                             b_cur[nt >> 1][(nt & 1) * 2 + 1]);

            if (kc < 3) {   // rotate (register-renamed by full unroll)
                #pragma unroll
                for (int mt = 0; mt < 2; mt++)
                    #pragma unroll
                    for (int e = 0; e < 4; e++) a_cur[mt][e] = a_nxt[mt][e];
                #pragma unroll
                for (int p = 0; p < 4; p++)
                    #pragma unroll
                    for (int e = 0; e < 4; e++) b_cur[p][e] = b_nxt[p][e];
            }
        }

        if (ch < 2) {
            __syncthreads();   // all warps done reading this buffer
            stage_chunk(sbase, ch & 1, ch + 2, Ag, Bg, tid);        // g3, g4
        } else if (ch == 2) {
            __syncthreads();   // buf0's last operand read is done
            stage_text_half(sbase, tg + (size_t)64 * B * 4, B, tid); // g5 -> buf0
        }
    }

    // ---- epilogue: all-smem |text - cos| with i<j mask ----
    asm volatile("cp.async.wait_group 0;" ::: "memory");
    __syncthreads();

    const int qrow = lane >> 2;          // 0..7
    const int qcol = (lane & 3) * 2;     // 0,2,4,6
    const bool diag = (bx == by);
    // rows 0-63 live at TEXT0_OFF, rows 64-127 at offset 0 (buf0)
    const float* __restrict__ Ts = reinterpret_cast<const float*>(
        smem + (wr < 2 ? TEXT0_OFF : 0));

    float acc = 0.0f;
    #pragma unroll
    for (int mt = 0; mt < 2; mt++) {
        const int r0 = wr * 32 + mt * 16 + qrow;        // tile rows r0, r0+8
        const int lr = r0 & 63;                          // row within half
        #pragma unroll
        for (int nt = 0; nt < 8; nt++) {
            const int cc = wc * 64 + nt * 8 + qcol;
            const float2 t0 = *reinterpret_cast<const float2*>(Ts + lr * LDM_T + cc);
            const float2 t1 = *reinterpret_cast<const float2*>(Ts + (lr + 8) * LDM_T + cc);
            const float* cf = c[mt][nt];
            if (!diag) {
                acc += fabsf(t0.x - cf[0]) + fabsf(t0.y - cf[1])
                     + fabsf(t1.x - cf[2]) + fabsf(t1.y - cf[3]);
            } else {
                if (cc     > r0)     acc += fabsf(t0.x - cf[0]);
                if (cc + 1 > r0)     acc += fabsf(t0.y - cf[1]);
                if (cc     > r0 + 8) acc += fabsf(t1.x - cf[2]);
                if (cc + 1 > r0 + 8) acc += fabsf(t1.y - cf[3]);
            }
        }
    }

    // ---- reduction: warp shuffle -> smem -> one atomicAdd ----
    #pragma unroll
    for (int o = 16; o > 0; o >>= 1) acc += __shfl_xor_sync(0xffffffffu, acc, o);

    __shared__ float red[8];
    if ((tid & 31) == 0) red[tid >> 5] = acc;
    __syncthreads();
    if (tid == 0) {
        float s = 0.0f;
        #pragma unroll
        for (int w = 0; w < 8; w++) s += red[w];
        atomicAdd(out, s * scale);
    }
}

// ---------------------------------------------------------------------------
// Launch
// ---------------------------------------------------------------------------
extern "C" void kernel_launch(void* const* d_in, const int* in_sizes, int n_in,
                              void* d_out, int out_size) {
    const float* emb  = (const float*)d_in[0];   // [B, D] fp32
    const float* text = (const float*)d_in[1];   // [B, B] fp32
    float* out = (float*)d_out;

    const int B = (int)(sqrt((double)in_sizes[1]) + 0.5);   // 8192
    const double count = (double)B * (double)(B - 1) / 2.0;
    const float scale = (float)(0.1 / count);

    cudaFuncSetAttribute(loss_kernel,
                         cudaFuncAttributeMaxDynamicSharedMemorySize, SMEM_TOTAL);

    normalize_kernel<<<B / 8, 256>>>(emb, B, out);

    const int NT = B / 128;
    const int nblocks = NT * (NT + 1) / 2;   // 2080 upper-tri tiles
    loss_kernel<<<nblocks, 256, SMEM_TOTAL>>>(text, out, B, scale);
}

// round 10
// speedup vs baseline: 1.5004x; 1.5004x over previous
#include <cuda_runtime.h>
#include <cuda_bf16.h>
#include <cstdint>
#include <math.h>

// Normalized embeddings scratch (bf16): 8192 * 256 * 2B = 4 MB, L2-resident.
__device__ __nv_bfloat16 g_en[8192 * 256];

// ---------------------------------------------------------------------------
// Kernel 1: row-normalize embeddings (fp32 -> bf16). One warp per row, D=256.
// Also zeroes the (poisoned) output scalar from block 0.
// ---------------------------------------------------------------------------
__global__ void normalize_kernel(const float* __restrict__ emb, int B,
                                 float* __restrict__ out) {
    if (blockIdx.x == 0 && threadIdx.x == 0) out[0] = 0.0f;

    const int warpId = threadIdx.x >> 5;
    const int lane   = threadIdx.x & 31;
    const int row    = blockIdx.x * 8 + warpId;
    if (row >= B) return;

    const float4* p = reinterpret_cast<const float4*>(emb + (size_t)row * 256);
    float4 v0 = p[lane];
    float4 v1 = p[lane + 32];

    float ss = v0.x * v0.x + v0.y * v0.y + v0.z * v0.z + v0.w * v0.w
             + v1.x * v1.x + v1.y * v1.y + v1.z * v1.z + v1.w * v1.w;
    #pragma unroll
    for (int o = 16; o > 0; o >>= 1) ss += __shfl_xor_sync(0xffffffffu, ss, o);

    const float scale = 1.0f / fmaxf(sqrtf(ss), 1e-8f);

    __nv_bfloat162 a0 = __floats2bfloat162_rn(v0.x * scale, v0.y * scale);
    __nv_bfloat162 a1 = __floats2bfloat162_rn(v0.z * scale, v0.w * scale);
    __nv_bfloat162 b0 = __floats2bfloat162_rn(v1.x * scale, v1.y * scale);
    __nv_bfloat162 b1 = __floats2bfloat162_rn(v1.z * scale, v1.w * scale);

    uint2 ua, ub;
    ua.x = *reinterpret_cast<unsigned*>(&a0);
    ua.y = *reinterpret_cast<unsigned*>(&a1);
    ub.x = *reinterpret_cast<unsigned*>(&b0);
    ub.y = *reinterpret_cast<unsigned*>(&b1);

    uint2* orow = reinterpret_cast<uint2*>(g_en + (size_t)row * 256);
    orow[lane]      = ua;
    orow[lane + 32] = ub;
}

// ---------------------------------------------------------------------------
// Kernel 2: fused cos-GEMM tile + |text - cos| masked reduction.
// mma.sync.m16n8k16 (bf16 -> fp32). B-fragment-only software pipeline:
// b(kc+1) LDSMs issue before the MMA block of kc (register-budget-safe;
// full a+b pipelining spills at the 128-reg / 2-CTA budget).
//
// One CTA = one 128x128 upper-triangular tile, K = 256 as four K=64 chunks,
// double-buffered cp.async. text_sim tile fully prefetched via cp.async:
//   group2 = text rows 0-63  -> dedicated TEXT0 region
//   group5 = text rows 64-127 -> buf0 (reused after its last operand read)
// Wait ladder: ch0/ch1 wait 2 | ch2/ch3 wait 1 | epilogue wait 0.
// smem = 2*36864 + 33792 = 105 KB -> 2 CTAs/SM.
// ---------------------------------------------------------------------------
#define LDM_OP     72                      // bf16 elems per padded chunk row
#define ROW_BYTES  144
#define STRIP_B    (128 * ROW_BYTES)       // 18432
#define BUF_B      (2 * STRIP_B)           // 36864 (A strip + B strip)
#define LDM_T      132                     // fp32 elems per padded text row
#define TROW_B     528
#define TEXT0_OFF  (2 * BUF_B)             // 73728
#define TEXT_HALF_B (64 * TROW_B)          // 33792
#define SMEM_TOTAL (TEXT0_OFF + TEXT_HALF_B)   // 107520

#define LDSM4(R0, R1, R2, R3, ADDR)                                          \
    asm volatile("ldmatrix.sync.aligned.m8n8.x4.shared.b16 {%0,%1,%2,%3}, [%4];" \
                 : "=r"(R0), "=r"(R1), "=r"(R2), "=r"(R3) : "r"(ADDR))

#define MMA16816(C, A, B0, B1)                                               \
    asm volatile("mma.sync.aligned.m16n8k16.row.col.f32.bf16.bf16.f32 "      \
                 "{%0,%1,%2,%3}, {%4,%5,%6,%7}, {%8,%9}, {%0,%1,%2,%3};"     \
                 : "+f"((C)[0]), "+f"((C)[1]), "+f"((C)[2]), "+f"((C)[3])    \
                 : "r"((A)[0]), "r"((A)[1]), "r"((A)[2]), "r"((A)[3]),       \
                   "r"(B0), "r"(B1))

// Stage one K=64 operand chunk (A + B strips) into buffer `buf`, commit.
__device__ __forceinline__ void stage_chunk(uint32_t sbase, int buf, int ch,
                                            const char* Ag, const char* Bg,
                                            int tid) {
    const uint32_t aDst = sbase + (uint32_t)buf * BUF_B;
    const uint32_t bDst = aDst + STRIP_B;
    const size_t gchunk = (size_t)ch * 128;
    #pragma unroll
    for (int i = tid; i < 1024; i += 256) {           // 128 rows x 8 x 16B
        const int r = i >> 3;
        const int c = i & 7;
        const uint32_t soff = (uint32_t)r * ROW_BYTES + (uint32_t)c * 16;
        const size_t   goff = (size_t)r * 512 + gchunk + (size_t)c * 16;
        asm volatile("cp.async.cg.shared.global [%0], [%1], 16;"
                     :: "r"(aDst + soff), "l"(Ag + goff) : "memory");
        asm volatile("cp.async.cg.shared.global [%0], [%1], 16;"
                     :: "r"(bDst + soff), "l"(Bg + goff) : "memory");
    }
    asm volatile("cp.async.commit_group;" ::: "memory");
}

// Stage 64 text rows (128 floats each) into smem at `dst` (528 B rows), commit.
__device__ __forceinline__ void stage_text_half(uint32_t dst, const char* tg,
                                                int B, int tid) {
    #pragma unroll
    for (int i = tid; i < 2048; i += 256) {           // 64 rows x 32 x 16B
        const int r = i >> 5;
        const int c = i & 31;
        asm volatile("cp.async.cg.shared.global [%0], [%1], 16;"
                     :: "r"(dst + (uint32_t)r * TROW_B + (uint32_t)c * 16),
                        "l"(tg + (size_t)r * B * 4 + (size_t)c * 16)
                     : "memory");
    }
    asm volatile("cp.async.commit_group;" ::: "memory");
}

__global__ __launch_bounds__(256, 2)
void loss_kernel(const float* __restrict__ text, float* __restrict__ out,
                 int B, float scale) {
    extern __shared__ char smem[];
    uint32_t sbase;
    asm("{ .reg .u64 t; cvta.to.shared.u64 t, %1; cvt.u32.u64 %0, t; }"
        : "=r"(sbase) : "l"((const void*)smem));

    const int tid = threadIdx.x;

    // ---- linear block id -> upper-triangular (by, bx), by <= bx ----
    const int NT = B >> 7;
    int t = blockIdx.x;
    int by = 0;
    while (t >= NT - by) { t -= NT - by; ++by; }
    const int bx = by + t;

    const char* __restrict__ Ag =
        reinterpret_cast<const char*>(g_en + (size_t)by * 128 * 256);
    const char* __restrict__ Bg =
        reinterpret_cast<const char*>(g_en + (size_t)bx * 128 * 256);
    const char* __restrict__ tg = reinterpret_cast<const char*>(
        text + (size_t)(by * 128) * B + (size_t)bx * 128);

    // ---- prologue: g0 = ch0, g1 = ch1, g2 = text rows 0-63 ----
    stage_chunk(sbase, 0, 0, Ag, Bg, tid);
    stage_chunk(sbase, 1, 1, Ag, Bg, tid);
    stage_text_half(sbase + TEXT0_OFF, tg, B, tid);

    // ---- warp / fragment geometry ----
    const int warpId = tid >> 5;
    const int lane   = tid & 31;
    const int wr = warpId & 3;    // 32-row strip
    const int wc = warpId >> 2;   // 64-col strip
    const int grp = lane >> 3;

    const uint32_t aOff =
        (uint32_t)(((wr * 32 + (lane & 15)) * LDM_OP + (lane >> 4) * 8) * 2);
    const uint32_t bOff = (uint32_t)STRIP_B +
        (uint32_t)(((wc * 64 + (grp >> 1) * 8 + (lane & 7)) * LDM_OP + (grp & 1) * 8) * 2);

    float c[2][8][4];
    #pragma unroll
    for (int mt = 0; mt < 2; mt++)
        #pragma unroll
        for (int nt = 0; nt < 8; nt++)
            #pragma unroll
            for (int e = 0; e < 4; e++) c[mt][nt][e] = 0.0f;

    // ---- mainloop over 4 K-chunks, B-fragment-pipelined inner loop ----
    #pragma unroll
    for (int ch = 0; ch < 4; ch++) {
        if (ch < 2) {
            asm volatile("cp.async.wait_group 2;" ::: "memory");
        } else {
            asm volatile("cp.async.wait_group 1;" ::: "memory");
        }
        __syncthreads();

        const uint32_t bufBase = sbase + (uint32_t)(ch & 1) * BUF_B;

        // preload B fragments for kc = 0
        uint32_t b_cur[4][4];
        #pragma unroll
        for (int p = 0; p < 4; p++)
            LDSM4(b_cur[p][0], b_cur[p][1], b_cur[p][2], b_cur[p][3],
                  bufBase + bOff + (uint32_t)(p * 16 * ROW_BYTES));

        #pragma unroll
        for (int kc = 0; kc < 4; kc++) {
            const uint32_t koff = (uint32_t)(kc * 32);   // 16 bf16 = 32 B

            // A fragments for this kc (latency covered by the b_nxt LDSMs
            // issued right after, before the first MMA consumes a[0])
            uint32_t a[2][4];
            #pragma unroll
            for (int mt = 0; mt < 2; mt++)
                LDSM4(a[mt][0], a[mt][1], a[mt][2], a[mt][3],
                      bufBase + aOff + (uint32_t)(mt * 16 * ROW_BYTES) + koff);

            // prefetch B fragments for kc+1; overlaps the MMA block below
            uint32_t b_nxt[4][4];
            if (kc < 3) {
                const uint32_t koff2 = koff + 32;
                #pragma unroll
                for (int p = 0; p < 4; p++)
                    LDSM4(b_nxt[p][0], b_nxt[p][1], b_nxt[p][2], b_nxt[p][3],
                          bufBase + bOff + (uint32_t)(p * 16 * ROW_BYTES) + koff2);
            }

            #pragma unroll
            for (int mt = 0; mt < 2; mt++)
                #pragma unroll
                for (int nt = 0; nt < 8; nt++)
                    MMA16816(c[mt][nt], a[mt],
                             b_cur[nt >> 1][(nt & 1) * 2],
                             b_cur[nt >> 1][(nt & 1) * 2 + 1]);

            if (kc < 3) {   // rotate (renamed away by the full unroll)
                #pragma unroll
                for (int p = 0; p < 4; p++)
                    #pragma unroll
                    for (int e = 0; e < 4; e++) b_cur[p][e] = b_nxt[p][e];
            }
        }

        if (ch < 2) {
            __syncthreads();   // all warps done reading this buffer
            stage_chunk(sbase, ch & 1, ch + 2, Ag, Bg, tid);        // g3, g4
        } else if (ch == 2) {
            __syncthreads();   // buf0's last operand read is done
            stage_text_half(sbase, tg + (size_t)64 * B * 4, B, tid); // g5 -> buf0
        }
    }

    // ---- epilogue: all-smem |text - cos| with i<j mask ----
    asm volatile("cp.async.wait_group 0;" ::: "memory");
    __syncthreads();

    const int qrow = lane >> 2;          // 0..7
    const int qcol = (lane & 3) * 2;     // 0,2,4,6
    const bool diag = (bx == by);
    // rows 0-63 live at TEXT0_OFF, rows 64-127 at offset 0 (buf0)
    const float* __restrict__ Ts = reinterpret_cast<const float*>(
        smem + (wr < 2 ? TEXT0_OFF : 0));

    float acc = 0.0f;
    #pragma unroll
    for (int mt = 0; mt < 2; mt++) {
        const int r0 = wr * 32 + mt * 16 + qrow;        // tile rows r0, r0+8
        const int lr = r0 & 63;                          // row within half
        #pragma unroll
        for (int nt = 0; nt < 8; nt++) {
            const int cc = wc * 64 + nt * 8 + qcol;
            const float2 t0 = *reinterpret_cast<const float2*>(Ts + lr * LDM_T + cc);
            const float2 t1 = *reinterpret_cast<const float2*>(Ts + (lr + 8) * LDM_T + cc);
            const float* cf = c[mt][nt];
            if (!diag) {
                acc += fabsf(t0.x - cf[0]) + fabsf(t0.y - cf[1])
                     + fabsf(t1.x - cf[2]) + fabsf(t1.y - cf[3]);
            } else {
                if (cc     > r0)     acc += fabsf(t0.x - cf[0]);
                if (cc + 1 > r0)     acc += fabsf(t0.y - cf[1]);
                if (cc     > r0 + 8) acc += fabsf(t1.x - cf[2]);
                if (cc + 1 > r0 + 8) acc += fabsf(t1.y - cf[3]);
            }
        }
    }

    // ---- reduction: warp shuffle -> smem -> one atomicAdd ----
    #pragma unroll
    for (int o = 16; o > 0; o >>= 1) acc += __shfl_xor_sync(0xffffffffu, acc, o);

    __shared__ float red[8];
    if ((tid & 31) == 0) red[tid >> 5] = acc;
    __syncthreads();
    if (tid == 0) {
        float s = 0.0f;
        #pragma unroll
        for (int w = 0; w < 8; w++) s += red[w];
        atomicAdd(out, s * scale);
    }
}

// ---------------------------------------------------------------------------
// Launch
// ---------------------------------------------------------------------------
extern "C" void kernel_launch(void* const* d_in, const int* in_sizes, int n_in,
                              void* d_out, int out_size) {
    const float* emb  = (const float*)d_in[0];   // [B, D] fp32
    const float* text = (const float*)d_in[1];   // [B, B] fp32
    float* out = (float*)d_out;

    const int B = (int)(sqrt((double)in_sizes[1]) + 0.5);   // 8192
    const double count = (double)B * (double)(B - 1) / 2.0;
    const float scale = (float)(0.1 / count);

    cudaFuncSetAttribute(loss_kernel,
                         cudaFuncAttributeMaxDynamicSharedMemorySize, SMEM_TOTAL);

    normalize_kernel<<<B / 8, 256>>>(emb, B, out);

    const int NT = B / 128;
    const int nblocks = NT * (NT + 1) / 2;   // 2080 upper-tri tiles
    loss_kernel<<<nblocks, 256, SMEM_TOTAL>>>(text, out, B, scale);
}